// round 12
// baseline (speedup 1.0000x reference)
#include <cuda_runtime.h>
#include <math.h>

#define BB 16
#define Q  8400
#define CC 80
#define G  64
#define RADIUS (2.5f/32.0f)
#define NWORD ((Q+31)/32)
#define Q4 (Q/4)
#define QPB 16
#define NBLK (Q/QPB)          // 525 full blocks (8400 % 16 == 0)

// ---- scratch (static device globals; no runtime allocation) ----
__device__ float              g_cost[(long long)BB*G*Q];       // [b][g][q]
__device__ unsigned long long g_mask[BB*Q];                    // per-anchor GT bitmask
__device__ int                g_rowarg[BB*Q];                  // argmin_g cost0[q][g]
__device__ unsigned           g_bmp [BB*NWORD];                // prologue-matched bitmap
__device__ int                g_cnt [BB*G];                    // per-column match count
__device__ float              g_piou[(long long)BB*G*NBLK*10]; // per-block top-10 iou
__device__ unsigned long long g_pcst[(long long)BB*G*NBLK*10]; // per-block bottom-10 packed (cost,q)

__device__ __forceinline__ unsigned ordf(float v) {
    unsigned u = __float_as_uint(v);
    return (u & 0x80000000u) ? ~u : (u | 0x80000000u);
}

// =====================================================================
// Kernel A: warp-per-anchor cost build; fast transcendentals; epilogue
// emits per-block top-10 iou and bottom-10 (cost,q) partials per column.
// =====================================================================
#define TBA 512
__global__ void __launch_bounds__(TBA)
build_cost_kernel(const float* __restrict__ logits,
                  const float* __restrict__ boxes,
                  const int*   __restrict__ labels,
                  const float* __restrict__ gtboxes)
{
    int b = blockIdx.y;
    int blk = blockIdx.x;
    int qbase = blk * QPB;
    int t = threadIdx.x;
    int w = t >> 5, l = t & 31;

    if (blk == 0 && t < G) g_cnt[b*G + t] = 0;

    __shared__ float4 s_gx4[G];
    __shared__ float  s_cx[G], s_cy[G], s_area[G];
    __shared__ int    s_lab[G];
    __shared__ float  s_cost[G][QPB+1];
    __shared__ float  s_iou [G][QPB+1];

    if (t < G) {
        float4 gb = ((const float4*)gtboxes)[b*G + t];
        s_cx[t]=gb.x; s_cy[t]=gb.y;
        float x0=gb.x-0.5f*gb.z, y0=gb.y-0.5f*gb.w;
        float x1=gb.x+0.5f*gb.z, y1=gb.y+0.5f*gb.w;
        s_gx4[t] = make_float4(x0,y0,x1,y1);
        s_area[t]=(x1-x0)*(y1-y0);
        s_lab[t]=labels[b*G+t];
    }
    __syncthreads();

    int q = qbase + w;
    {
        float4 pb = ((const float4*)boxes)[b*Q + q];
        float ax = pb.x, ay = pb.y;
        float bx0 = pb.x-0.5f*pb.z, by0 = pb.y-0.5f*pb.w;
        float bx1 = pb.x+0.5f*pb.z, by1 = pb.y+0.5f*pb.w;
        float areaA = (bx1-bx0)*(by1-by0);
        const float* lrow = logits + ((long long)b*Q + q)*CC;

        float costv[2];
        bool  anyflag = false;
        bool  iibcv[2];

        #pragma unroll
        for (int h=0; h<2; h++) {
            int g = l + h*32;
            float4 gx = s_gx4[g];
            bool ib = (ax>gx.x) && (ax<gx.z) && (ay>gx.y) && (ay<gx.w);
            bool ic = (ax>s_cx[g]-RADIUS)&&(ax<s_cx[g]+RADIUS)&&
                      (ay>s_cy[g]-RADIUS)&&(ay<s_cy[g]+RADIUS);
            anyflag |= (ib | ic);
            iibcv[h] = ib && ic;
        }
        unsigned ball = __ballot_sync(0xffffffffu, anyflag);
        float fgterm = ball ? 0.0f : 10000.0f;

        #pragma unroll
        for (int h=0; h<2; h++) {
            int g = l + h*32;
            float x = __ldg(lrow + s_lab[g]);
            float p = __fdividef(1.0f, 1.0f + __expf(-x));
            float neg = 0.75f * p*p * (-__logf(1.0f - p + 1e-8f));
            float pos = 0.25f * (1.0f-p)*(1.0f-p) * (-__logf(p + 1e-8f));
            float cls = pos - neg;

            float4 gx = s_gx4[g];
            float ltx=fmaxf(bx0,gx.x), lty=fmaxf(by0,gx.y);
            float rbx=fminf(bx1,gx.z), rby=fminf(by1,gx.w);
            float iw=fmaxf(rbx-ltx,0.0f), ih=fmaxf(rby-lty,0.0f);
            float inter = iw*ih;
            float uni   = areaA + s_area[g] - inter;
            float iou   = __fdividef(inter, uni);
            float ex0=fminf(bx0,gx.x), ey0=fminf(by0,gx.y);
            float ex1=fmaxf(bx1,gx.z), ey1=fmaxf(by1,gx.w);
            float encl = fmaxf(ex1-ex0,0.0f)*fmaxf(ey1-ey0,0.0f);
            float giou = iou - __fdividef(encl - uni, encl);

            costv[h] = cls - 3.0f*giou + (iibcv[h] ? 0.0f : 100.0f) + fgterm;
            s_cost[g][w] = costv[h];
            s_iou [g][w] = iou;
        }

        float bv; int bg;
        if (costv[1] < costv[0]) { bv = costv[1]; bg = l+32; }
        else                     { bv = costv[0]; bg = l;    }
        #pragma unroll
        for (int off=16; off; off>>=1) {
            float ov = __shfl_down_sync(0xffffffffu, bv, off);
            int   og = __shfl_down_sync(0xffffffffu, bg, off);
            if (ov < bv || (ov==bv && og < bg)) { bv=ov; bg=og; }
        }
        if (l==0) {
            g_rowarg[b*Q+q] = bg;
            g_mask  [b*Q+q] = 0ULL;
        }
    }
    __syncthreads();

    // --- epilogue 1: vectorized cost store (t < 256) ---
    if (t < 256) {
        int r = t >> 2, j4 = (t & 3)*4;
        float4 v = make_float4(s_cost[r][j4], s_cost[r][j4+1],
                               s_cost[r][j4+2], s_cost[r][j4+3]);
        *(float4*)(g_cost + ((long long)b*G + r)*Q + qbase + j4) = v;
    }
    // --- epilogue 2: per-column top-10 iou of this block's 16 anchors ---
    else if (t < 256 + G) {
        int g = t - 256;
        float top[10];
        #pragma unroll
        for (int i=0;i<10;i++) top[i] = -INFINITY;
        #pragma unroll
        for (int j=0;j<QPB;j++) {
            float nv = s_iou[g][j];
            if (nv > top[9]) {
                #pragma unroll
                for (int i=0;i<10;i++) {
                    float cur = top[i];
                    bool take = nv > cur;
                    top[i] = take ? nv : cur;
                    nv     = take ? cur : nv;
                }
            }
        }
        float* dst = g_piou + ((long long)(b*G + g)*NBLK + blk)*10;
        #pragma unroll
        for (int i=0;i<10;i++) dst[i] = top[i];
    }
    // --- epilogue 3: per-column bottom-10 packed (cost,q) ---
    else if (t < 256 + 2*G) {
        int g = t - 256 - G;
        unsigned long long pk[10];
        #pragma unroll
        for (int i=0;i<10;i++) pk[i] = 0xFFFFFFFFFFFFFFFFULL;
        #pragma unroll
        for (int j=0;j<QPB;j++) {
            unsigned long long nv =
                ((unsigned long long)ordf(s_cost[g][j]) << 32) | (unsigned)(qbase + j);
            if (nv < pk[9]) {
                #pragma unroll
                for (int i=0;i<10;i++) {
                    unsigned long long cur = pk[i];
                    bool take = nv < cur;
                    pk[i] = take ? nv : cur;
                    nv    = take ? cur : nv;
                }
            }
        }
        unsigned long long* dst = g_pcst + ((long long)(b*G + g)*NBLK + blk)*10;
        #pragma unroll
        for (int i=0;i<10;i++) dst[i] = pk[i];
    }
}

// =====================================================================
// Kernel B: merge partials per column -> dyn_k + mask bits.
// 5250 elements per column instead of 8400 full IoU recomputes.
// =====================================================================
#define TKB 256
__global__ void __launch_bounds__(TKB)
merge_kernel()
{
    int b = blockIdx.x >> 6, g = blockIdx.x & 63;
    const float* piou = g_piou + (long long)(b*G + g)*NBLK*10;
    const unsigned long long* pcst = g_pcst + (long long)(b*G + g)*NBLK*10;
    int t = threadIdx.x;
    const int NE = NBLK*10;   // 5250

    __shared__ float              s_iv[TKB*10];
    __shared__ unsigned long long s_pk[TKB*10];

    float itop[10];
    unsigned long long pk[10];
    #pragma unroll
    for (int i=0;i<10;i++) { itop[i]=-INFINITY; pk[i]=0xFFFFFFFFFFFFFFFFULL; }

    for (int i=t; i<NE; i+=TKB) {
        float nv = __ldg(piou + i);
        if (nv > itop[9]) {
            #pragma unroll
            for (int k=0;k<10;k++) {
                float cur = itop[k];
                bool take = nv > cur;
                itop[k] = take ? nv : cur;
                nv      = take ? cur : nv;
            }
        }
        unsigned long long cv = __ldg(pcst + i);
        if (cv < pk[9]) {
            #pragma unroll
            for (int k=0;k<10;k++) {
                unsigned long long cur = pk[k];
                bool take = cv < cur;
                pk[k] = take ? cv : cur;
                cv    = take ? cur : cv;
            }
        }
    }

    #pragma unroll
    for (int i=0;i<10;i++) { s_iv[t*10+i]=itop[i]; s_pk[t*10+i]=pk[i]; }
    __syncthreads();

    for (int s=TKB/2; s>=1; s>>=1) {
        if (t < s) {
            int o = (t+s)*10;
            // iou top-10: valley combine + odd-even sort desc
            float ci[10];
            #pragma unroll
            for (int i=0;i<10;i++) ci[i] = fmaxf(itop[i], s_iv[o+9-i]);
            #pragma unroll
            for (int r=0;r<10;r++) {
                #pragma unroll
                for (int i=0;i<9;i++) {
                    if (((i^r)&1)==0) {
                        float a=ci[i], c2=ci[i+1];
                        ci[i]=fmaxf(a,c2); ci[i+1]=fminf(a,c2);
                    }
                }
            }
            #pragma unroll
            for (int i=0;i<10;i++) itop[i]=ci[i];

            // packed cost bottom-10: valley combine + odd-even sort asc
            unsigned long long cp[10];
            #pragma unroll
            for (int i=0;i<10;i++) {
                unsigned long long a = pk[i], c2 = s_pk[o+9-i];
                cp[i] = (a < c2) ? a : c2;
            }
            #pragma unroll
            for (int r=0;r<10;r++) {
                #pragma unroll
                for (int i=0;i<9;i++) {
                    if (((i^r)&1)==0) {
                        unsigned long long a=cp[i], c2=cp[i+1];
                        bool sw = a > c2;
                        cp[i]   = sw ? c2 : a;
                        cp[i+1] = sw ? a  : c2;
                    }
                }
            }
            #pragma unroll
            for (int i=0;i<10;i++) pk[i]=cp[i];

            #pragma unroll
            for (int i=0;i<10;i++) { s_iv[t*10+i]=itop[i]; s_pk[t*10+i]=pk[i]; }
        }
        __syncthreads();
    }

    if (t==0) {
        float ssum = 0.0f;
        #pragma unroll
        for (int i=0;i<10;i++) ssum += itop[i];
        int k = (int)ssum;
        if (k < 1) k = 1;
        if (k > 10) k = 10;
        for (int j=0; j<k; j++) {
            int qm = (int)(pk[j] & 0xFFFFFFFFULL);
            atomicOr(&g_mask[b*Q + qm], 1ULL<<g);
        }
    }
}

// =====================================================================
// Kernel C1: prep — segment blocks; warp-per-word dedup + ballot bitmap.
// =====================================================================
#define SEGN 8
#define SEGW ((NWORD + SEGN - 1)/SEGN)
#define TDP 1024
__global__ void __launch_bounds__(TDP)
prep_kernel()
{
    int b = blockIdx.x, seg = blockIdx.y, t = threadIdx.x;
    int wid = t >> 5, lane = t & 31;
    int w0 = seg*SEGW, w1 = min(w0 + SEGW, NWORD);

    for (int w = w0 + wid; w < w1; w += TDP/32) {
        int q = w*32 + lane;
        bool matched = false;
        if (q < Q) {
            unsigned long long m = g_mask[b*Q+q];
            if (__popcll(m) > 1) {
                m = 1ULL << g_rowarg[b*Q+q];
                g_mask[b*Q+q] = m;
            }
            if (m) {
                matched = true;
                unsigned long long mm = m;
                while (mm) { int g = __ffsll((long long)mm)-1; atomicAdd(&g_cnt[b*G+g],1); mm &= mm-1; }
            }
        }
        unsigned word = __ballot_sync(0xffffffffu, matched);
        if (lane == 0) g_bmp[b*NWORD + w] = word;
    }
}

// =====================================================================
// Kernel C2: colmin — one block per (b,g); unmatched columns only.
// =====================================================================
#define TCM 256
__global__ void __launch_bounds__(TCM)
colmin_kernel()
{
    int b = blockIdx.x >> 6, g = blockIdx.x & 63;
    if (g_cnt[b*G+g] != 0) return;
    int t = threadIdx.x;
    const float4* cg4 = (const float4*)(g_cost + ((long long)b*G+g)*Q);
    const unsigned* bmp = g_bmp + b*NWORD;

    __shared__ float s_rv[TCM];
    __shared__ int   s_ri[TCM];

    float bv = INFINITY; int bi = Q;
    for (int i=t; i<Q4; i+=TCM) {
        unsigned nib = (bmp[i>>3] >> ((i&7)*4)) & 0xFu;
        float4 c = __ldg(cg4 + i);
        int q0 = i*4;
        if (!(nib & 1u) && c.x < bv) { bv=c.x; bi=q0;   }
        if (!(nib & 2u) && c.y < bv) { bv=c.y; bi=q0+1; }
        if (!(nib & 4u) && c.z < bv) { bv=c.z; bi=q0+2; }
        if (!(nib & 8u) && c.w < bv) { bv=c.w; bi=q0+3; }
    }
    s_rv[t]=bv; s_ri[t]=bi;
    __syncthreads();
    for (int s=TCM/2; s>=1; s>>=1) {
        if (t < s) {
            float ov=s_rv[t+s]; int oi=s_ri[t+s];
            if (ov < s_rv[t] || (ov==s_rv[t] && oi < s_ri[t])) { s_rv[t]=ov; s_ri[t]=oi; }
        }
        __syncthreads();
    }
    if (t==0 && s_ri[0] < Q)
        atomicOr(&g_mask[b*Q + s_ri[0]], 1ULL<<g);
}

// =====================================================================
// Kernel C3: output — sel/asn per row; out_mq via packed smem atomicMin.
// =====================================================================
#define TDO 1024
__global__ void __launch_bounds__(TDO)
output_kernel(char* __restrict__ out_bytes, int layoutB)
{
    int b = blockIdx.x, t = threadIdx.x;
    const float* cost = g_cost + (long long)b*G*Q;
    const unsigned* bmp = g_bmp + b*NWORD;

    __shared__ unsigned long long s_pk[G];
    __shared__ int s_un;
    if (t < G) s_pk[t] = 0xFFFFFFFFFFFFFFFFULL;
    if (t == 0) s_un = 0;
    __syncthreads();
    if (t < G && g_cnt[b*G+t] == 0) s_un = 1;
    __syncthreads();
    float penT = s_un ? 100000.0f : 0.0f;

    unsigned char* out_sel8 = (unsigned char*)out_bytes;
    int*   out_asnI = (int*)(out_bytes + (size_t)BB*Q);
    int*   out_mqI  = (int*)(out_bytes + (size_t)BB*Q + (size_t)4*BB*Q);
    float* outF     = (float*)out_bytes;

    for (int q=t; q<Q; q+=TDO) {
        unsigned long long m = g_mask[b*Q+q];
        if (layoutB) {
            out_sel8[b*Q+q] = m ? 1 : 0;
            out_asnI[b*Q+q] = m ? (__ffsll((long long)m)-1) : 0;
        } else {
            outF[b*Q+q]        = m ? 1.0f : 0.0f;
            outF[BB*Q + b*Q+q] = m ? (float)(__ffsll((long long)m)-1) : 0.0f;
        }
        if (m) {
            float pen = ((bmp[q>>5] >> (q&31)) & 1u) ? penT : 0.0f;
            unsigned long long mm = m;
            while (mm) {
                int g = __ffsll((long long)mm)-1; mm &= mm-1;
                float v = cost[(long long)g*Q + q] + pen;
                unsigned long long pkv = ((unsigned long long)ordf(v) << 32) | (unsigned)q;
                atomicMin(&s_pk[g], pkv);
            }
        }
    }
    __syncthreads();
    if (t < G) {
        int qmin = (int)(s_pk[t] & 0xFFFFFFFFULL);
        if (layoutB) out_mqI[b*G+t] = qmin;
        else         outF[2*BB*Q + b*G+t] = (float)qmin;
    }
}

// =====================================================================
extern "C" void kernel_launch(void* const* d_in, const int* in_sizes, int n_in,
                              void* d_out, int out_size)
{
    const float* logits = 0; const float* boxes = 0;
    const int*   labels = 0; const float* gtb   = 0;
    for (int i = 0; i < n_in; i++) {
        switch (in_sizes[i]) {
            case BB*Q*CC: logits = (const float*)d_in[i]; break;
            case BB*Q*4:  boxes  = (const float*)d_in[i]; break;
            case BB*G:    labels = (const int*)  d_in[i]; break;
            case BB*G*4:  gtb    = (const float*)d_in[i]; break;
        }
    }

    int layoutB = (out_size == BB*Q + 4*BB*Q + 4*BB*G) ? 1 : 0;

    dim3 gA(NBLK, BB);
    build_cost_kernel<<<gA, TBA>>>(logits, boxes, labels, gtb);
    merge_kernel<<<BB*G, TKB>>>();
    dim3 gP(BB, SEGN);
    prep_kernel<<<gP, TDP>>>();
    colmin_kernel<<<BB*G, TCM>>>();
    output_kernel<<<BB, TDO>>>((char*)d_out, layoutB);
}

// round 13
// speedup vs baseline: 1.2966x; 1.2966x over previous
#include <cuda_runtime.h>
#include <math.h>

#define BB 16
#define Q  8400
#define CC 80
#define G  64
#define RADIUS (2.5f/32.0f)
#define NWORD ((Q+31)/32)
#define Q4 (Q/4)
#define QPB 16
#define NBLK (Q/QPB)          // 525 (8400 % 16 == 0)

// ---- scratch (static device globals; no runtime allocation) ----
__device__ float              g_cost[(long long)BB*G*Q];   // [b][g][q]
__device__ float              g_iou [(long long)BB*G*Q];   // [b][g][q]
__device__ unsigned long long g_mask[BB*Q];                // per-anchor GT bitmask
__device__ int                g_rowarg[BB*Q];              // argmin_g cost0[q][g]
__device__ unsigned           g_bmp [BB*NWORD];            // prologue-matched bitmap
__device__ int                g_cnt [BB*G];                // per-column match count

__device__ __forceinline__ unsigned ordf(float v) {
    unsigned u = __float_as_uint(v);
    return (u & 0x80000000u) ? ~u : (u | 0x80000000u);
}

// =====================================================================
// Kernel A: warp-per-anchor cost build; fast transcendentals; stores
// BOTH cost and iou column-major (vectorized epilogue, all 512 threads).
// =====================================================================
#define TBA 512
__global__ void __launch_bounds__(TBA)
build_cost_kernel(const float* __restrict__ logits,
                  const float* __restrict__ boxes,
                  const int*   __restrict__ labels,
                  const float* __restrict__ gtboxes)
{
    int b = blockIdx.y;
    int qbase = blockIdx.x * QPB;
    int t = threadIdx.x;
    int w = t >> 5, l = t & 31;

    if (blockIdx.x == 0 && t < G) g_cnt[b*G + t] = 0;

    __shared__ float4 s_gx4[G];
    __shared__ float  s_cx[G], s_cy[G], s_area[G];
    __shared__ int    s_lab[G];
    __shared__ float  s_cost[G][QPB+1];
    __shared__ float  s_iou [G][QPB+1];

    if (t < G) {
        float4 gb = ((const float4*)gtboxes)[b*G + t];
        s_cx[t]=gb.x; s_cy[t]=gb.y;
        float x0=gb.x-0.5f*gb.z, y0=gb.y-0.5f*gb.w;
        float x1=gb.x+0.5f*gb.z, y1=gb.y+0.5f*gb.w;
        s_gx4[t] = make_float4(x0,y0,x1,y1);
        s_area[t]=(x1-x0)*(y1-y0);
        s_lab[t]=labels[b*G+t];
    }
    __syncthreads();

    int q = qbase + w;
    {
        float4 pb = ((const float4*)boxes)[b*Q + q];
        float ax = pb.x, ay = pb.y;
        float bx0 = pb.x-0.5f*pb.z, by0 = pb.y-0.5f*pb.w;
        float bx1 = pb.x+0.5f*pb.z, by1 = pb.y+0.5f*pb.w;
        float areaA = (bx1-bx0)*(by1-by0);
        const float* lrow = logits + ((long long)b*Q + q)*CC;

        float costv[2];
        bool  anyflag = false;
        bool  iibcv[2];

        #pragma unroll
        for (int h=0; h<2; h++) {
            int g = l + h*32;
            float4 gx = s_gx4[g];
            bool ib = (ax>gx.x) && (ax<gx.z) && (ay>gx.y) && (ay<gx.w);
            bool ic = (ax>s_cx[g]-RADIUS)&&(ax<s_cx[g]+RADIUS)&&
                      (ay>s_cy[g]-RADIUS)&&(ay<s_cy[g]+RADIUS);
            anyflag |= (ib | ic);
            iibcv[h] = ib && ic;
        }
        unsigned ball = __ballot_sync(0xffffffffu, anyflag);
        float fgterm = ball ? 0.0f : 10000.0f;

        #pragma unroll
        for (int h=0; h<2; h++) {
            int g = l + h*32;
            float x = __ldg(lrow + s_lab[g]);
            float p = __fdividef(1.0f, 1.0f + __expf(-x));
            float neg = 0.75f * p*p * (-__logf(1.0f - p + 1e-8f));
            float pos = 0.25f * (1.0f-p)*(1.0f-p) * (-__logf(p + 1e-8f));
            float cls = pos - neg;

            float4 gx = s_gx4[g];
            float ltx=fmaxf(bx0,gx.x), lty=fmaxf(by0,gx.y);
            float rbx=fminf(bx1,gx.z), rby=fminf(by1,gx.w);
            float iw=fmaxf(rbx-ltx,0.0f), ih=fmaxf(rby-lty,0.0f);
            float inter = iw*ih;
            float uni   = areaA + s_area[g] - inter;
            float iou   = __fdividef(inter, uni);
            float ex0=fminf(bx0,gx.x), ey0=fminf(by0,gx.y);
            float ex1=fmaxf(bx1,gx.z), ey1=fmaxf(by1,gx.w);
            float encl = fmaxf(ex1-ex0,0.0f)*fmaxf(ey1-ey0,0.0f);
            float giou = iou - __fdividef(encl - uni, encl);

            costv[h] = cls - 3.0f*giou + (iibcv[h] ? 0.0f : 100.0f) + fgterm;
            s_cost[g][w] = costv[h];
            s_iou [g][w] = iou;
        }

        float bv; int bg;
        if (costv[1] < costv[0]) { bv = costv[1]; bg = l+32; }
        else                     { bv = costv[0]; bg = l;    }
        #pragma unroll
        for (int off=16; off; off>>=1) {
            float ov = __shfl_down_sync(0xffffffffu, bv, off);
            int   og = __shfl_down_sync(0xffffffffu, bg, off);
            if (ov < bv || (ov==bv && og < bg)) { bv=ov; bg=og; }
        }
        if (l==0) {
            g_rowarg[b*Q+q] = bg;
            g_mask  [b*Q+q] = 0ULL;
        }
    }
    __syncthreads();

    // vectorized transpose stores: 256 threads cost, 256 threads iou
    if (t < 256) {
        int r = t >> 2, j4 = (t & 3)*4;
        float4 v = make_float4(s_cost[r][j4], s_cost[r][j4+1],
                               s_cost[r][j4+2], s_cost[r][j4+3]);
        *(float4*)(g_cost + ((long long)b*G + r)*Q + qbase + j4) = v;
    } else {
        int tt = t - 256;
        int r = tt >> 2, j4 = (tt & 3)*4;
        float4 v = make_float4(s_iou[r][j4], s_iou[r][j4+1],
                               s_iou[r][j4+2], s_iou[r][j4+3]);
        *(float4*)(g_iou + ((long long)b*G + r)*Q + qbase + j4) = v;
    }
}

// =====================================================================
// Kernel B: per (b,g) column select; pure two-stream float4 scan (no
// box math, no divides); register-resident lists and merges.
// =====================================================================
#define TKB 256
__global__ void __launch_bounds__(TKB)
select_kernel()
{
    int b = blockIdx.x >> 6, g = blockIdx.x & 63;
    const float4* cost4 = (const float4*)(g_cost + ((long long)b*G+g)*Q);
    const float4* iou4  = (const float4*)(g_iou  + ((long long)b*G+g)*Q);
    int t = threadIdx.x;

    __shared__ float s_iv[TKB*10];
    __shared__ float s_pv[TKB*10];
    __shared__ int   s_pi[TKB*10];

    float itop[10];
    float pv[10]; int pi[10];
    #pragma unroll
    for (int i=0;i<10;i++) { itop[i]=-INFINITY; pv[i]=INFINITY; pi[i]=0x7FFFFFFF; }

    for (int i=t; i<Q4; i+=TKB) {
        float4 iv4 = __ldg(iou4 + i);
        float4 cv4 = __ldg(cost4 + i);
        int q0 = i*4;
        #pragma unroll
        for (int j=0; j<4; j++) {
            float iou = (j==0)?iv4.x:(j==1)?iv4.y:(j==2)?iv4.z:iv4.w;
            if (iou > itop[9]) {
                float nv = iou;
                #pragma unroll
                for (int k=0;k<10;k++) {
                    float cur = itop[k];
                    bool take = nv > cur;
                    itop[k] = take ? nv : cur;
                    nv      = take ? cur : nv;
                }
            }
            float v = (j==0)?cv4.x:(j==1)?cv4.y:(j==2)?cv4.z:cv4.w;
            if (v < pv[9]) {
                float nv = v; int ni = q0 + j;
                #pragma unroll
                for (int k=0;k<10;k++) {
                    float cvk = pv[k]; int cik = pi[k];
                    bool take = (nv < cvk) || (nv == cvk && ni < cik);
                    pv[k] = take ? nv : cvk;  pi[k] = take ? ni : cik;
                    nv    = take ? cvk : nv;  ni    = take ? cik : ni;
                }
            }
        }
    }

    #pragma unroll
    for (int i=0;i<10;i++) {
        s_iv[t*10+i]=itop[i]; s_pv[t*10+i]=pv[i]; s_pi[t*10+i]=pi[i];
    }
    __syncthreads();

    for (int s=TKB/2; s>=1; s>>=1) {
        if (t < s) {
            int o = (t+s)*10;
            float ci[10];
            #pragma unroll
            for (int i=0;i<10;i++) ci[i] = fmaxf(itop[i], s_iv[o+9-i]);
            #pragma unroll
            for (int r=0;r<10;r++) {
                #pragma unroll
                for (int i=0;i<9;i++) {
                    if (((i^r)&1)==0) {
                        float a=ci[i], c2=ci[i+1];
                        ci[i]=fmaxf(a,c2); ci[i+1]=fminf(a,c2);
                    }
                }
            }
            #pragma unroll
            for (int i=0;i<10;i++) itop[i]=ci[i];

            float cv[10]; int cx[10];
            #pragma unroll
            for (int i=0;i<10;i++) {
                float ov2 = s_pv[o+9-i]; int oi2 = s_pi[o+9-i];
                bool mineWins = (pv[i] < ov2) || (pv[i]==ov2 && pi[i] < oi2);
                cv[i] = mineWins ? pv[i] : ov2;
                cx[i] = mineWins ? pi[i] : oi2;
            }
            #pragma unroll
            for (int r=0;r<10;r++) {
                #pragma unroll
                for (int i=0;i<9;i++) {
                    if (((i^r)&1)==0) {
                        float a=cv[i], c2=cv[i+1];
                        int   ai=cx[i], ci2=cx[i+1];
                        bool sw = (a > c2) || (a==c2 && ai > ci2);
                        cv[i]   = sw ? c2 : a;   cv[i+1] = sw ? a  : c2;
                        cx[i]   = sw ? ci2: ai;  cx[i+1] = sw ? ai : ci2;
                    }
                }
            }
            #pragma unroll
            for (int i=0;i<10;i++) { pv[i]=cv[i]; pi[i]=cx[i]; }

            #pragma unroll
            for (int i=0;i<10;i++) {
                s_iv[t*10+i]=itop[i]; s_pv[t*10+i]=pv[i]; s_pi[t*10+i]=pi[i];
            }
        }
        __syncthreads();
    }

    if (t==0) {
        float ssum = 0.0f;
        #pragma unroll
        for (int i=0;i<10;i++) ssum += itop[i];
        int k = (int)ssum;
        if (k < 1) k = 1;
        if (k > 10) k = 10;
        for (int j=0; j<k; j++)
            atomicOr(&g_mask[b*Q + pi[j]], 1ULL<<g);
    }
}

// =====================================================================
// Kernel C1: prep — segment blocks; warp-per-word dedup + ballot bitmap.
// =====================================================================
#define SEGN 8
#define SEGW ((NWORD + SEGN - 1)/SEGN)
#define TDP 1024
__global__ void __launch_bounds__(TDP)
prep_kernel()
{
    int b = blockIdx.x, seg = blockIdx.y, t = threadIdx.x;
    int wid = t >> 5, lane = t & 31;
    int w0 = seg*SEGW, w1 = min(w0 + SEGW, NWORD);

    for (int w = w0 + wid; w < w1; w += TDP/32) {
        int q = w*32 + lane;
        bool matched = false;
        if (q < Q) {
            unsigned long long m = g_mask[b*Q+q];
            if (__popcll(m) > 1) {
                m = 1ULL << g_rowarg[b*Q+q];
                g_mask[b*Q+q] = m;
            }
            if (m) {
                matched = true;
                unsigned long long mm = m;
                while (mm) { int g = __ffsll((long long)mm)-1; atomicAdd(&g_cnt[b*G+g],1); mm &= mm-1; }
            }
        }
        unsigned word = __ballot_sync(0xffffffffu, matched);
        if (lane == 0) g_bmp[b*NWORD + w] = word;
    }
}

// =====================================================================
// Kernel C2: colmin — one block per (b,g); unmatched columns only.
// =====================================================================
#define TCM 256
__global__ void __launch_bounds__(TCM)
colmin_kernel()
{
    int b = blockIdx.x >> 6, g = blockIdx.x & 63;
    if (g_cnt[b*G+g] != 0) return;
    int t = threadIdx.x;
    const float4* cg4 = (const float4*)(g_cost + ((long long)b*G+g)*Q);
    const unsigned* bmp = g_bmp + b*NWORD;

    __shared__ float s_rv[TCM];
    __shared__ int   s_ri[TCM];

    float bv = INFINITY; int bi = Q;
    for (int i=t; i<Q4; i+=TCM) {
        unsigned nib = (bmp[i>>3] >> ((i&7)*4)) & 0xFu;
        float4 c = __ldg(cg4 + i);
        int q0 = i*4;
        if (!(nib & 1u) && c.x < bv) { bv=c.x; bi=q0;   }
        if (!(nib & 2u) && c.y < bv) { bv=c.y; bi=q0+1; }
        if (!(nib & 4u) && c.z < bv) { bv=c.z; bi=q0+2; }
        if (!(nib & 8u) && c.w < bv) { bv=c.w; bi=q0+3; }
    }
    s_rv[t]=bv; s_ri[t]=bi;
    __syncthreads();
    for (int s=TCM/2; s>=1; s>>=1) {
        if (t < s) {
            float ov=s_rv[t+s]; int oi=s_ri[t+s];
            if (ov < s_rv[t] || (ov==s_rv[t] && oi < s_ri[t])) { s_rv[t]=ov; s_ri[t]=oi; }
        }
        __syncthreads();
    }
    if (t==0 && s_ri[0] < Q)
        atomicOr(&g_mask[b*Q + s_ri[0]], 1ULL<<g);
}

// =====================================================================
// Kernel C3: output — sel/asn per row; out_mq via packed smem atomicMin.
// =====================================================================
#define TDO 1024
__global__ void __launch_bounds__(TDO)
output_kernel(char* __restrict__ out_bytes, int layoutB)
{
    int b = blockIdx.x, t = threadIdx.x;
    const float* cost = g_cost + (long long)b*G*Q;
    const unsigned* bmp = g_bmp + b*NWORD;

    __shared__ unsigned long long s_pk[G];
    __shared__ int s_un;
    if (t < G) s_pk[t] = 0xFFFFFFFFFFFFFFFFULL;
    if (t == 0) s_un = 0;
    __syncthreads();
    if (t < G && g_cnt[b*G+t] == 0) s_un = 1;
    __syncthreads();
    float penT = s_un ? 100000.0f : 0.0f;

    unsigned char* out_sel8 = (unsigned char*)out_bytes;
    int*   out_asnI = (int*)(out_bytes + (size_t)BB*Q);
    int*   out_mqI  = (int*)(out_bytes + (size_t)BB*Q + (size_t)4*BB*Q);
    float* outF     = (float*)out_bytes;

    for (int q=t; q<Q; q+=TDO) {
        unsigned long long m = g_mask[b*Q+q];
        if (layoutB) {
            out_sel8[b*Q+q] = m ? 1 : 0;
            out_asnI[b*Q+q] = m ? (__ffsll((long long)m)-1) : 0;
        } else {
            outF[b*Q+q]        = m ? 1.0f : 0.0f;
            outF[BB*Q + b*Q+q] = m ? (float)(__ffsll((long long)m)-1) : 0.0f;
        }
        if (m) {
            float pen = ((bmp[q>>5] >> (q&31)) & 1u) ? penT : 0.0f;
            unsigned long long mm = m;
            while (mm) {
                int g = __ffsll((long long)mm)-1; mm &= mm-1;
                float v = cost[(long long)g*Q + q] + pen;
                unsigned long long pkv = ((unsigned long long)ordf(v) << 32) | (unsigned)q;
                atomicMin(&s_pk[g], pkv);
            }
        }
    }
    __syncthreads();
    if (t < G) {
        int qmin = (int)(s_pk[t] & 0xFFFFFFFFULL);
        if (layoutB) out_mqI[b*G+t] = qmin;
        else         outF[2*BB*Q + b*G+t] = (float)qmin;
    }
}

// =====================================================================
extern "C" void kernel_launch(void* const* d_in, const int* in_sizes, int n_in,
                              void* d_out, int out_size)
{
    const float* logits = 0; const float* boxes = 0;
    const int*   labels = 0; const float* gtb   = 0;
    for (int i = 0; i < n_in; i++) {
        switch (in_sizes[i]) {
            case BB*Q*CC: logits = (const float*)d_in[i]; break;
            case BB*Q*4:  boxes  = (const float*)d_in[i]; break;
            case BB*G:    labels = (const int*)  d_in[i]; break;
            case BB*G*4:  gtb    = (const float*)d_in[i]; break;
        }
    }

    int layoutB = (out_size == BB*Q + 4*BB*Q + 4*BB*G) ? 1 : 0;

    dim3 gA(NBLK, BB);
    build_cost_kernel<<<gA, TBA>>>(logits, boxes, labels, gtb);
    select_kernel<<<BB*G, TKB>>>();
    dim3 gP(BB, SEGN);
    prep_kernel<<<gP, TDP>>>();
    colmin_kernel<<<BB*G, TCM>>>();
    output_kernel<<<BB, TDO>>>((char*)d_out, layoutB);
}

// round 14
// speedup vs baseline: 1.2969x; 1.0002x over previous
#include <cuda_runtime.h>
#include <math.h>

#define BB 16
#define Q  8400
#define CC 80
#define G  64
#define RADIUS (2.5f/32.0f)
#define NWORD ((Q+31)/32)
#define Q4 (Q/4)
#define QPB 16
#define NBLK (Q/QPB)          // 525 (8400 % 16 == 0)

// ---- scratch (static device globals; no runtime allocation) ----
__device__ float              g_cost[(long long)BB*G*Q];   // [b][g][q]
__device__ float              g_iou [(long long)BB*G*Q];   // [b][g][q]
__device__ unsigned long long g_mask[BB*Q];                // per-anchor GT bitmask
__device__ int                g_rowarg[BB*Q];              // argmin_g cost0[q][g]
__device__ unsigned           g_bmp [BB*NWORD];            // prologue-matched bitmap
__device__ int                g_cnt [BB*G];                // per-column match count

__device__ __forceinline__ unsigned ordf(float v) {
    unsigned u = __float_as_uint(v);
    return (u & 0x80000000u) ? ~u : (u | 0x80000000u);
}

// =====================================================================
// Kernel A: warp-per-anchor cost build; SINGLE pass over GTs; algebraic
// focal cost (3 MUFU/pair); fg-term added uniformly in the epilogue.
// =====================================================================
#define TBA 512
__global__ void __launch_bounds__(TBA)
build_cost_kernel(const float* __restrict__ logits,
                  const float* __restrict__ boxes,
                  const int*   __restrict__ labels,
                  const float* __restrict__ gtboxes)
{
    int b = blockIdx.y;
    int qbase = blockIdx.x * QPB;
    int t = threadIdx.x;
    int w = t >> 5, l = t & 31;

    if (blockIdx.x == 0 && t < G) g_cnt[b*G + t] = 0;

    __shared__ float4 s_gx4[G];
    __shared__ float  s_cx[G], s_cy[G], s_area[G];
    __shared__ int    s_lab[G];
    __shared__ float  s_cost[G][QPB+1];
    __shared__ float  s_iou [G][QPB+1];
    __shared__ float  s_fg  [QPB];

    if (t < G) {
        float4 gb = ((const float4*)gtboxes)[b*G + t];
        s_cx[t]=gb.x; s_cy[t]=gb.y;
        float x0=gb.x-0.5f*gb.z, y0=gb.y-0.5f*gb.w;
        float x1=gb.x+0.5f*gb.z, y1=gb.y+0.5f*gb.w;
        s_gx4[t] = make_float4(x0,y0,x1,y1);
        s_area[t]=(x1-x0)*(y1-y0);
        s_lab[t]=labels[b*G+t];
    }
    __syncthreads();

    int q = qbase + w;
    {
        float4 pb = ((const float4*)boxes)[b*Q + q];
        float ax = pb.x, ay = pb.y;
        float bx0 = pb.x-0.5f*pb.z, by0 = pb.y-0.5f*pb.w;
        float bx1 = pb.x+0.5f*pb.z, by1 = pb.y+0.5f*pb.w;
        float areaA = (bx1-bx0)*(by1-by0);
        const float* lrow = logits + ((long long)b*Q + q)*CC;

        float costv[2];
        bool  anyflag = false;

        #pragma unroll
        for (int h=0; h<2; h++) {
            int g = l + h*32;
            float4 gx = s_gx4[g];

            // geometry flags
            bool ib = (ax>gx.x) && (ax<gx.z) && (ay>gx.y) && (ay<gx.w);
            bool ic = (ax>s_cx[g]-RADIUS)&&(ax<s_cx[g]+RADIUS)&&
                      (ay>s_cy[g]-RADIUS)&&(ay<s_cy[g]+RADIUS);
            anyflag |= (ib | ic);
            bool iibc = ib && ic;

            // focal class cost (algebraic form):
            //  t=e^{-x}, d=1+t, p=1/d, L=log d;  -log p = L; -log(1-p)=x+L
            float x  = __ldg(lrow + s_lab[g]);
            float tt = __expf(-x);
            float d  = 1.0f + tt;
            float p  = __fdividef(1.0f, d);
            float L  = __logf(d);
            float omp = tt * p;                    // 1-p
            float pos = 0.25f * (omp*omp) * L;
            float neg = 0.75f * (p*p) * (x + L);
            float cls = pos - neg;

            // iou / giou
            float ltx=fmaxf(bx0,gx.x), lty=fmaxf(by0,gx.y);
            float rbx=fminf(bx1,gx.z), rby=fminf(by1,gx.w);
            float iw=fmaxf(rbx-ltx,0.0f), ih=fmaxf(rby-lty,0.0f);
            float inter = iw*ih;
            float uni   = areaA + s_area[g] - inter;
            float iou   = __fdividef(inter, uni);
            float ex0=fminf(bx0,gx.x), ey0=fminf(by0,gx.y);
            float ex1=fmaxf(bx1,gx.z), ey1=fmaxf(by1,gx.w);
            float encl = fmaxf(ex1-ex0,0.0f)*fmaxf(ey1-ey0,0.0f);
            float giou = iou - __fdividef(encl - uni, encl);

            costv[h] = cls - 3.0f*giou + (iibc ? 0.0f : 100.0f);
            s_cost[g][w] = costv[h];
            s_iou [g][w] = iou;
        }

        unsigned ball = __ballot_sync(0xffffffffu, anyflag);

        // row argmin on cost-without-fg (fg is row-uniform -> same argmin)
        float bv; int bg;
        if (costv[1] < costv[0]) { bv = costv[1]; bg = l+32; }
        else                     { bv = costv[0]; bg = l;    }
        #pragma unroll
        for (int off=16; off; off>>=1) {
            float ov = __shfl_down_sync(0xffffffffu, bv, off);
            int   og = __shfl_down_sync(0xffffffffu, bg, off);
            if (ov < bv || (ov==bv && og < bg)) { bv=ov; bg=og; }
        }
        if (l==0) {
            s_fg[w] = ball ? 0.0f : 10000.0f;
            g_rowarg[b*Q+q] = bg;
            g_mask  [b*Q+q] = 0ULL;
        }
    }
    __syncthreads();

    // vectorized transpose stores: 256 threads cost(+fg), 256 threads iou
    if (t < 256) {
        int r = t >> 2, j4 = (t & 3)*4;
        float4 v = make_float4(s_cost[r][j4]   + s_fg[j4],
                               s_cost[r][j4+1] + s_fg[j4+1],
                               s_cost[r][j4+2] + s_fg[j4+2],
                               s_cost[r][j4+3] + s_fg[j4+3]);
        *(float4*)(g_cost + ((long long)b*G + r)*Q + qbase + j4) = v;
    } else {
        int tt = t - 256;
        int r = tt >> 2, j4 = (tt & 3)*4;
        float4 v = make_float4(s_iou[r][j4], s_iou[r][j4+1],
                               s_iou[r][j4+2], s_iou[r][j4+3]);
        *(float4*)(g_iou + ((long long)b*G + r)*Q + qbase + j4) = v;
    }
}

// =====================================================================
// Kernel B: per (b,g) column select; pure two-stream float4 scan;
// register-resident lists and merges.
// =====================================================================
#define TKB 256
__global__ void __launch_bounds__(TKB)
select_kernel()
{
    int b = blockIdx.x >> 6, g = blockIdx.x & 63;
    const float4* cost4 = (const float4*)(g_cost + ((long long)b*G+g)*Q);
    const float4* iou4  = (const float4*)(g_iou  + ((long long)b*G+g)*Q);
    int t = threadIdx.x;

    __shared__ float s_iv[TKB*10];
    __shared__ float s_pv[TKB*10];
    __shared__ int   s_pi[TKB*10];

    float itop[10];
    float pv[10]; int pi[10];
    #pragma unroll
    for (int i=0;i<10;i++) { itop[i]=-INFINITY; pv[i]=INFINITY; pi[i]=0x7FFFFFFF; }

    for (int i=t; i<Q4; i+=TKB) {
        float4 iv4 = __ldg(iou4 + i);
        float4 cv4 = __ldg(cost4 + i);
        int q0 = i*4;
        #pragma unroll
        for (int j=0; j<4; j++) {
            float iou = (j==0)?iv4.x:(j==1)?iv4.y:(j==2)?iv4.z:iv4.w;
            if (iou > itop[9]) {
                float nv = iou;
                #pragma unroll
                for (int k=0;k<10;k++) {
                    float cur = itop[k];
                    bool take = nv > cur;
                    itop[k] = take ? nv : cur;
                    nv      = take ? cur : nv;
                }
            }
            float v = (j==0)?cv4.x:(j==1)?cv4.y:(j==2)?cv4.z:cv4.w;
            if (v < pv[9]) {
                float nv = v; int ni = q0 + j;
                #pragma unroll
                for (int k=0;k<10;k++) {
                    float cvk = pv[k]; int cik = pi[k];
                    bool take = (nv < cvk) || (nv == cvk && ni < cik);
                    pv[k] = take ? nv : cvk;  pi[k] = take ? ni : cik;
                    nv    = take ? cvk : nv;  ni    = take ? cik : ni;
                }
            }
        }
    }

    #pragma unroll
    for (int i=0;i<10;i++) {
        s_iv[t*10+i]=itop[i]; s_pv[t*10+i]=pv[i]; s_pi[t*10+i]=pi[i];
    }
    __syncthreads();

    for (int s=TKB/2; s>=1; s>>=1) {
        if (t < s) {
            int o = (t+s)*10;
            float ci[10];
            #pragma unroll
            for (int i=0;i<10;i++) ci[i] = fmaxf(itop[i], s_iv[o+9-i]);
            #pragma unroll
            for (int r=0;r<10;r++) {
                #pragma unroll
                for (int i=0;i<9;i++) {
                    if (((i^r)&1)==0) {
                        float a=ci[i], c2=ci[i+1];
                        ci[i]=fmaxf(a,c2); ci[i+1]=fminf(a,c2);
                    }
                }
            }
            #pragma unroll
            for (int i=0;i<10;i++) itop[i]=ci[i];

            float cv[10]; int cx[10];
            #pragma unroll
            for (int i=0;i<10;i++) {
                float ov2 = s_pv[o+9-i]; int oi2 = s_pi[o+9-i];
                bool mineWins = (pv[i] < ov2) || (pv[i]==ov2 && pi[i] < oi2);
                cv[i] = mineWins ? pv[i] : ov2;
                cx[i] = mineWins ? pi[i] : oi2;
            }
            #pragma unroll
            for (int r=0;r<10;r++) {
                #pragma unroll
                for (int i=0;i<9;i++) {
                    if (((i^r)&1)==0) {
                        float a=cv[i], c2=cv[i+1];
                        int   ai=cx[i], ci2=cx[i+1];
                        bool sw = (a > c2) || (a==c2 && ai > ci2);
                        cv[i]   = sw ? c2 : a;   cv[i+1] = sw ? a  : c2;
                        cx[i]   = sw ? ci2: ai;  cx[i+1] = sw ? ai : ci2;
                    }
                }
            }
            #pragma unroll
            for (int i=0;i<10;i++) { pv[i]=cv[i]; pi[i]=cx[i]; }

            #pragma unroll
            for (int i=0;i<10;i++) {
                s_iv[t*10+i]=itop[i]; s_pv[t*10+i]=pv[i]; s_pi[t*10+i]=pi[i];
            }
        }
        __syncthreads();
    }

    if (t==0) {
        float ssum = 0.0f;
        #pragma unroll
        for (int i=0;i<10;i++) ssum += itop[i];
        int k = (int)ssum;
        if (k < 1) k = 1;
        if (k > 10) k = 10;
        for (int j=0; j<k; j++)
            atomicOr(&g_mask[b*Q + pi[j]], 1ULL<<g);
    }
}

// =====================================================================
// Kernel C1: prep — segment blocks; warp-per-word dedup + ballot bitmap.
// =====================================================================
#define SEGN 8
#define SEGW ((NWORD + SEGN - 1)/SEGN)
#define TDP 1024
__global__ void __launch_bounds__(TDP)
prep_kernel()
{
    int b = blockIdx.x, seg = blockIdx.y, t = threadIdx.x;
    int wid = t >> 5, lane = t & 31;
    int w0 = seg*SEGW, w1 = min(w0 + SEGW, NWORD);

    for (int w = w0 + wid; w < w1; w += TDP/32) {
        int q = w*32 + lane;
        bool matched = false;
        if (q < Q) {
            unsigned long long m = g_mask[b*Q+q];
            if (__popcll(m) > 1) {
                m = 1ULL << g_rowarg[b*Q+q];
                g_mask[b*Q+q] = m;
            }
            if (m) {
                matched = true;
                unsigned long long mm = m;
                while (mm) { int g = __ffsll((long long)mm)-1; atomicAdd(&g_cnt[b*G+g],1); mm &= mm-1; }
            }
        }
        unsigned word = __ballot_sync(0xffffffffu, matched);
        if (lane == 0) g_bmp[b*NWORD + w] = word;
    }
}

// =====================================================================
// Kernel C2: colmin — one block per (b,g); unmatched columns only.
// =====================================================================
#define TCM 256
__global__ void __launch_bounds__(TCM)
colmin_kernel()
{
    int b = blockIdx.x >> 6, g = blockIdx.x & 63;
    if (g_cnt[b*G+g] != 0) return;
    int t = threadIdx.x;
    const float4* cg4 = (const float4*)(g_cost + ((long long)b*G+g)*Q);
    const unsigned* bmp = g_bmp + b*NWORD;

    __shared__ float s_rv[TCM];
    __shared__ int   s_ri[TCM];

    float bv = INFINITY; int bi = Q;
    for (int i=t; i<Q4; i+=TCM) {
        unsigned nib = (bmp[i>>3] >> ((i&7)*4)) & 0xFu;
        float4 c = __ldg(cg4 + i);
        int q0 = i*4;
        if (!(nib & 1u) && c.x < bv) { bv=c.x; bi=q0;   }
        if (!(nib & 2u) && c.y < bv) { bv=c.y; bi=q0+1; }
        if (!(nib & 4u) && c.z < bv) { bv=c.z; bi=q0+2; }
        if (!(nib & 8u) && c.w < bv) { bv=c.w; bi=q0+3; }
    }
    s_rv[t]=bv; s_ri[t]=bi;
    __syncthreads();
    for (int s=TCM/2; s>=1; s>>=1) {
        if (t < s) {
            float ov=s_rv[t+s]; int oi=s_ri[t+s];
            if (ov < s_rv[t] || (ov==s_rv[t] && oi < s_ri[t])) { s_rv[t]=ov; s_ri[t]=oi; }
        }
        __syncthreads();
    }
    if (t==0 && s_ri[0] < Q)
        atomicOr(&g_mask[b*Q + s_ri[0]], 1ULL<<g);
}

// =====================================================================
// Kernel C3: output — sel/asn per row; out_mq via packed smem atomicMin.
// =====================================================================
#define TDO 1024
__global__ void __launch_bounds__(TDO)
output_kernel(char* __restrict__ out_bytes, int layoutB)
{
    int b = blockIdx.x, t = threadIdx.x;
    const float* cost = g_cost + (long long)b*G*Q;
    const unsigned* bmp = g_bmp + b*NWORD;

    __shared__ unsigned long long s_pk[G];
    __shared__ int s_un;
    if (t < G) s_pk[t] = 0xFFFFFFFFFFFFFFFFULL;
    if (t == 0) s_un = 0;
    __syncthreads();
    if (t < G && g_cnt[b*G+t] == 0) s_un = 1;
    __syncthreads();
    float penT = s_un ? 100000.0f : 0.0f;

    unsigned char* out_sel8 = (unsigned char*)out_bytes;
    int*   out_asnI = (int*)(out_bytes + (size_t)BB*Q);
    int*   out_mqI  = (int*)(out_bytes + (size_t)BB*Q + (size_t)4*BB*Q);
    float* outF     = (float*)out_bytes;

    for (int q=t; q<Q; q+=TDO) {
        unsigned long long m = g_mask[b*Q+q];
        if (layoutB) {
            out_sel8[b*Q+q] = m ? 1 : 0;
            out_asnI[b*Q+q] = m ? (__ffsll((long long)m)-1) : 0;
        } else {
            outF[b*Q+q]        = m ? 1.0f : 0.0f;
            outF[BB*Q + b*Q+q] = m ? (float)(__ffsll((long long)m)-1) : 0.0f;
        }
        if (m) {
            float pen = ((bmp[q>>5] >> (q&31)) & 1u) ? penT : 0.0f;
            unsigned long long mm = m;
            while (mm) {
                int g = __ffsll((long long)mm)-1; mm &= mm-1;
                float v = cost[(long long)g*Q + q] + pen;
                unsigned long long pkv = ((unsigned long long)ordf(v) << 32) | (unsigned)q;
                atomicMin(&s_pk[g], pkv);
            }
        }
    }
    __syncthreads();
    if (t < G) {
        int qmin = (int)(s_pk[t] & 0xFFFFFFFFULL);
        if (layoutB) out_mqI[b*G+t] = qmin;
        else         outF[2*BB*Q + b*G+t] = (float)qmin;
    }
}

// =====================================================================
extern "C" void kernel_launch(void* const* d_in, const int* in_sizes, int n_in,
                              void* d_out, int out_size)
{
    const float* logits = 0; const float* boxes = 0;
    const int*   labels = 0; const float* gtb   = 0;
    for (int i = 0; i < n_in; i++) {
        switch (in_sizes[i]) {
            case BB*Q*CC: logits = (const float*)d_in[i]; break;
            case BB*Q*4:  boxes  = (const float*)d_in[i]; break;
            case BB*G:    labels = (const int*)  d_in[i]; break;
            case BB*G*4:  gtb    = (const float*)d_in[i]; break;
        }
    }

    int layoutB = (out_size == BB*Q + 4*BB*Q + 4*BB*G) ? 1 : 0;

    dim3 gA(NBLK, BB);
    build_cost_kernel<<<gA, TBA>>>(logits, boxes, labels, gtb);
    select_kernel<<<BB*G, TKB>>>();
    dim3 gP(BB, SEGN);
    prep_kernel<<<gP, TDP>>>();
    colmin_kernel<<<BB*G, TCM>>>();
    output_kernel<<<BB, TDO>>>((char*)d_out, layoutB);
}